// round 16
// baseline (speedup 1.0000x reference)
#include <cuda_runtime.h>
#include <cuda_bf16.h>
#include <math.h>

// Problem constants
#define BB   32      // batch
#define SS   64      // src len
#define TT   64      // tgt len (63 decode steps)
#define EE   512     // embed dim
#define HH   512     // encoder hidden per dir
#define DDm  1024    // 2*H
#define VV   32000   // vocab

// ---------------------------------------------------------------------------
// Static device scratch
// ---------------------------------------------------------------------------
__device__ __align__(16) float g_embx [BB*SS*EE];
__device__ __align__(16) float g_xgF  [BB*SS*4*HH];
__device__ __align__(16) float g_xgB  [BB*SS*4*HH];
__device__ __align__(16) float g_in1  [BB*SS*DDm];
__device__ __align__(16) float g_enc  [BB*SS*DDm];
__device__ __align__(16) float g_Uenc [BB*SS*DDm];
__device__ __align__(16) float g_hbuf [2*2*2*BB*HH];   // [layer][dir][pp][b*HH+j]
__device__ __align__(16) float g_c    [2*2*BB*HH];
__device__ __align__(16) float g_dh0  [2*BB*DDm];      // ping-pong
__device__ __align__(16) float g_dc0  [BB*DDm];
__device__ __align__(16) float g_dh1  [2*BB*DDm];      // ping-pong
__device__ __align__(16) float g_dc1  [BB*DDm];
__device__ __align__(16) float g_q    [BB*DDm];
__device__ __align__(16) float g_sc   [BB*SS];
__device__ __align__(16) float g_xcat [BB*DDm];        // context only now
__device__ __align__(16) float g_H1   [63*BB*DDm];
__device__ __align__(16) float g_Gemb [2048*4*DDm];    // emb gate adds (+d0_b), rows t*32+b
__device__ unsigned g_barA, g_barC;

// converted activation buffers (u32 = packed bf16 pair, interleaved hi/lo)
__device__ __align__(16) unsigned g_embxc[BB*SS*EE];
__device__ __align__(16) unsigned g_in1c [BB*SS*DDm];
__device__ __align__(16) unsigned g_encc [BB*SS*DDm];
__device__ __align__(16) unsigned g_H1c  [2048*DDm];
__device__ __align__(16) unsigned g_embTc[2048*EE];    // converted target embeddings

// converted-weight pool
#define OFF_E0F_WIH 0ull
#define OFF_E0B_WIH (OFF_E0F_WIH + 2048ull*512)
#define OFF_E1F_WIH (OFF_E0B_WIH + 2048ull*512)
#define OFF_E1B_WIH (OFF_E1F_WIH + 2048ull*1024)
#define OFF_E0F_WHH (OFF_E1B_WIH + 2048ull*1024)
#define OFF_E0B_WHH (OFF_E0F_WHH + 2048ull*512)
#define OFF_E1F_WHH (OFF_E0B_WHH + 2048ull*512)
#define OFF_E1B_WHH (OFF_E1F_WHH + 2048ull*512)
#define OFF_UA      (OFF_E1B_WHH + 2048ull*512)
#define OFF_WA      (OFF_UA + 1024ull*1024)
#define OFF_D0WIHE  (OFF_WA + 1024ull*1024)            // d0_wih cols [0,512)
#define OFF_D0WIHC  (OFF_D0WIHE + 4096ull*512)         // d0_wih cols [512,1536)
#define OFF_D0WHH   (OFF_D0WIHC + 4096ull*1024)
#define OFF_D1WIH   (OFF_D0WHH + 4096ull*1024)
#define OFF_D1WHH   (OFF_D1WIH + 4096ull*1024)
#define OFF_FC      (OFF_D1WHH + 4096ull*1024)
#define WCVT_TOTAL  (OFF_FC + 32000ull*1024)
__device__ __align__(16) unsigned g_wcvt[WCVT_TOTAL];

__device__ __forceinline__ float sigf(float v) { return 1.0f/(1.0f + expf(-v)); }

__device__ __forceinline__ float tanha(float x) {
    float r; asm("tanh.approx.f32 %0, %1;" : "=f"(r) : "f"(x)); return r;
}

// fp32 pair -> packed (bf16 hi, bf16 lo)
__device__ __forceinline__ void cvt2(float f0, float f1, unsigned& hi, unsigned& lo) {
    __nv_bfloat16 h0 = __float2bfloat16(f0);
    __nv_bfloat16 h1 = __float2bfloat16(f1);
    __nv_bfloat16 l0 = __float2bfloat16(f0 - __bfloat162float(h0));
    __nv_bfloat16 l1 = __float2bfloat16(f1 - __bfloat162float(h1));
    hi = (unsigned)__bfloat16_as_ushort(h0) | ((unsigned)__bfloat16_as_ushort(h1) << 16);
    lo = (unsigned)__bfloat16_as_ushort(l0) | ((unsigned)__bfloat16_as_ushort(l1) << 16);
}

__device__ __forceinline__ void mma16816(float* c,
    unsigned a0, unsigned a1, unsigned a2, unsigned a3,
    unsigned b0, unsigned b1)
{
    asm volatile(
        "mma.sync.aligned.m16n8k16.row.col.f32.bf16.bf16.f32 "
        "{%0,%1,%2,%3}, {%4,%5,%6,%7}, {%8,%9}, {%0,%1,%2,%3};"
        : "+f"(c[0]), "+f"(c[1]), "+f"(c[2]), "+f"(c[3])
        : "r"(a0), "r"(a1), "r"(a2), "r"(a3), "r"(b0), "r"(b1));
}

// grid-wide software barrier (CG grid.sync pattern; counter monotone per call)
__device__ __forceinline__ void gwait(unsigned* ctr, unsigned tgt) {
    __syncthreads();
    if (threadIdx.x == 0) {
        asm volatile("red.release.gpu.add.u32 [%0], %1;" :: "l"(ctr), "r"(1u) : "memory");
        unsigned v;
        do {
            asm volatile("ld.acquire.gpu.u32 %0, [%1];" : "=r"(v) : "l"(ctr) : "memory");
        } while (v < tgt);
    }
    __syncthreads();
}

// ---------------------------------------------------------------------------
// conversions
// ---------------------------------------------------------------------------
__global__ void cvtW4(const float4* __restrict__ src, uint4* __restrict__ dst, int n4) {
    for (int i = blockIdx.x*blockDim.x + threadIdx.x; i < n4; i += gridDim.x*blockDim.x) {
        float4 v = src[i];
        unsigned h0, l0, h1, l1;
        cvt2(v.x, v.y, h0, l0);
        cvt2(v.z, v.w, h1, l1);
        dst[i] = make_uint4(h0, l0, h1, l1);
    }
}

// strided column-slice conversion: take cols [c0, c0+Kc) of rows with stride rs
__global__ void cvtW4s(const float* __restrict__ src, uint4* __restrict__ dst,
                       int rows, int rs, int c0, int Kc) {
    int n4 = rows * (Kc/4);
    for (int i = blockIdx.x*blockDim.x + threadIdx.x; i < n4; i += gridDim.x*blockDim.x) {
        int row = i / (Kc/4), cf = i % (Kc/4);
        float4 v = *(const float4*)(src + (size_t)row*rs + c0 + cf*4);
        unsigned h0, l0, h1, l1;
        cvt2(v.x, v.y, h0, l0);
        cvt2(v.z, v.w, h1, l1);
        dst[i] = make_uint4(h0, l0, h1, l1);
    }
}

// gather + convert target embeddings: row (t*32+b) -> emb_tgt[y[b][t]], pad zeros
__global__ void gath_tgt(const int* __restrict__ y, const float* __restrict__ emb_tgt) {
    int row = blockIdx.x;
    int t = row >> 5, b = row & 31;
    uint4* dst = (uint4*)(g_embTc + (size_t)row*EE);
    int i = threadIdx.x;   // 128 threads, EE/4 = 128 float4s
    if (t < TT-1) {
        float4 v = ((const float4*)(emb_tgt + (size_t)y[b*TT+t]*EE))[i];
        unsigned h0, l0, h1, l1;
        cvt2(v.x, v.y, h0, l0);
        cvt2(v.z, v.w, h1, l1);
        dst[i] = make_uint4(h0, l0, h1, l1);
    } else {
        dst[i] = make_uint4(0u, 0u, 0u, 0u);
    }
}

// ---------------------------------------------------------------------------
// embedding gather with source reversal
// ---------------------------------------------------------------------------
__global__ void embed_rev_kernel(const int* __restrict__ x,
                                 const float* __restrict__ emb_src) {
    int bs = blockIdx.x;
    int b = bs >> 6, s = bs & 63;
    int tok = x[b*SS + (SS-1 - s)];
    const float4* src = (const float4*)(emb_src + (size_t)tok*EE);
    float4* dst = (float4*)(g_embx + (size_t)bs*EE);
    for (int i = threadIdx.x; i < EE/4; i += blockDim.x) dst[i] = src[i];
}

// ---------------------------------------------------------------------------
// bgemm128: split-bf16 mma GEMM, BM=BN=128, BK=32, register prefetch.
// ---------------------------------------------------------------------------
__global__ __launch_bounds__(256) void bgemm128(
    const unsigned* __restrict__ Ahl, const unsigned* __restrict__ Whl,
    const float* __restrict__ bias, float* __restrict__ C,
    int Mtot, int N, int K, int remap, int mbase)
{
    __shared__ unsigned sAh[128][17], sAl[128][17];
    __shared__ unsigned sWh[128][17], sWl[128][17];

    int tid = threadIdx.x;
    int m0 = mbase + blockIdx.x * 128;
    int n0 = blockIdx.y * 128;

    int lane = tid & 31, wid = tid >> 5;
    int wm = (wid & 3) * 32;
    int wn = (wid >> 2) * 64;
    int grp = lane >> 2, q = lane & 3;

    float c[2][8][4];
    #pragma unroll
    for (int mf = 0; mf < 2; mf++)
        #pragma unroll
        for (int nf = 0; nf < 8; nf++)
            #pragma unroll
            for (int i = 0; i < 4; i++) c[mf][nf][i] = 0.f;

    int r  = tid >> 1;
    int ku = (tid & 1) * 16;
    int kp = (tid & 1) * 8;

    const unsigned* Arow = Ahl + (size_t)(m0 + r)*K + ku;
    const unsigned* Wrow = Whl + (size_t)(n0 + r)*K + ku;

    uint4 pa[4], pw[4];
    #pragma unroll
    for (int i = 0; i < 4; i++) {
        pa[i] = *(const uint4*)(Arow + i*4);
        pw[i] = *(const uint4*)(Wrow + i*4);
    }

    for (int k0 = 0; k0 < K; k0 += 32) {
        __syncthreads();
        #pragma unroll
        for (int i = 0; i < 4; i++) {
            sAh[r][kp+2*i]   = pa[i].x; sAl[r][kp+2*i]   = pa[i].y;
            sAh[r][kp+2*i+1] = pa[i].z; sAl[r][kp+2*i+1] = pa[i].w;
            sWh[r][kp+2*i]   = pw[i].x; sWl[r][kp+2*i]   = pw[i].y;
            sWh[r][kp+2*i+1] = pw[i].z; sWl[r][kp+2*i+1] = pw[i].w;
        }
        __syncthreads();
        if (k0 + 32 < K) {
            #pragma unroll
            for (int i = 0; i < 4; i++) {
                pa[i] = *(const uint4*)(Arow + k0 + 32 + i*4);
                pw[i] = *(const uint4*)(Wrow + k0 + 32 + i*4);
            }
        }

        #pragma unroll
        for (int ks = 0; ks < 2; ks++) {
            int k8 = ks*8;
            unsigned Ah0[2], Ah1[2], Ah2[2], Ah3[2];
            unsigned Al0[2], Al1[2], Al2[2], Al3[2];
            #pragma unroll
            for (int mf = 0; mf < 2; mf++) {
                int mb = wm + mf*16;
                Ah0[mf] = sAh[mb+grp  ][k8+q];   Ah1[mf] = sAh[mb+grp+8][k8+q];
                Ah2[mf] = sAh[mb+grp  ][k8+q+4]; Ah3[mf] = sAh[mb+grp+8][k8+q+4];
                Al0[mf] = sAl[mb+grp  ][k8+q];   Al1[mf] = sAl[mb+grp+8][k8+q];
                Al2[mf] = sAl[mb+grp  ][k8+q+4]; Al3[mf] = sAl[mb+grp+8][k8+q+4];
            }
            #pragma unroll
            for (int nf = 0; nf < 8; nf++) {
                int nb = wn + nf*8;
                unsigned Bh0 = sWh[nb+grp][k8+q], Bh1 = sWh[nb+grp][k8+q+4];
                unsigned Bl0 = sWl[nb+grp][k8+q], Bl1 = sWl[nb+grp][k8+q+4];
                #pragma unroll
                for (int mf = 0; mf < 2; mf++) {
                    mma16816(c[mf][nf], Ah0[mf],Ah1[mf],Ah2[mf],Ah3[mf], Bh0,Bh1);
                    mma16816(c[mf][nf], Ah0[mf],Ah1[mf],Ah2[mf],Ah3[mf], Bl0,Bl1);
                    mma16816(c[mf][nf], Al0[mf],Al1[mf],Al2[mf],Al3[mf], Bh0,Bh1);
                }
            }
        }
    }

    #pragma unroll
    for (int mf = 0; mf < 2; mf++) {
        #pragma unroll
        for (int nf = 0; nf < 8; nf++) {
            int gn = n0 + wn + nf*8 + q*2;
            float b0 = bias[gn], b1 = bias[gn+1];
            int gm0 = m0 + wm + mf*16 + grp;
            int gm1 = gm0 + 8;
            if (gm0 < Mtot) {
                int row = remap ? (gm0 & 31)*63 + (gm0 >> 5) : gm0;
                C[(size_t)row*N + gn]     = c[mf][nf][0] + b0;
                C[(size_t)row*N + gn + 1] = c[mf][nf][1] + b1;
            }
            if (gm1 < Mtot) {
                int row = remap ? (gm1 & 31)*63 + (gm1 >> 5) : gm1;
                C[(size_t)row*N + gn]     = c[mf][nf][2] + b0;
                C[(size_t)row*N + gn + 1] = c[mf][nf][3] + b1;
            }
        }
    }
}

// ---------------------------------------------------------------------------
// BM=32 K-loop, BK=128, double-buffered smem + register prefetch.
// ---------------------------------------------------------------------------
#define STG (4*2080)
__device__ __forceinline__ void kloop2(
    const float* __restrict__ Arow, const unsigned* __restrict__ Wrow, int K,
    unsigned* __restrict__ sm,
    float* cacc, int r, int c8, int mh, int wn, int grp, int qq, int& buf)
{
    float4 fa[4]; uint4 uw[4];
    #pragma unroll
    for (int i = 0; i < 4; i++) {
        fa[i] = *(const float4*)(Arow + (c8 + i*8)*4);
        uw[i] = *(const uint4*)(Wrow + (c8 + i*8)*4);
    }
    for (int k0 = 0; k0 < K; k0 += 128) {
        unsigned* sAh = sm + buf*STG;
        unsigned* sAl = sAh + 2080;
        unsigned* sWh = sAh + 4160;
        unsigned* sWl = sAh + 6240;
        #pragma unroll
        for (int i = 0; i < 4; i++) {
            int col = (c8 + i*8)*2;
            unsigned h0,l0,h1,l1;
            cvt2(fa[i].x, fa[i].y, h0, l0);
            cvt2(fa[i].z, fa[i].w, h1, l1);
            sAh[r*65+col]=h0; sAl[r*65+col]=l0; sAh[r*65+col+1]=h1; sAl[r*65+col+1]=l1;
            sWh[r*65+col]=uw[i].x; sWl[r*65+col]=uw[i].y;
            sWh[r*65+col+1]=uw[i].z; sWl[r*65+col+1]=uw[i].w;
        }
        __syncthreads();
        if (k0 + 128 < K) {
            #pragma unroll
            for (int i = 0; i < 4; i++) {
                fa[i] = *(const float4*)(Arow + k0 + 128 + (c8 + i*8)*4);
                uw[i] = *(const uint4*)(Wrow + k0 + 128 + (c8 + i*8)*4);
            }
        }
        #pragma unroll
        for (int ks = 0; ks < 8; ks++) {
            int k8 = ks*8;
            int mb = mh*16;
            unsigned Ah0 = sAh[(mb+grp)*65+k8+qq],   Ah1 = sAh[(mb+grp+8)*65+k8+qq];
            unsigned Ah2 = sAh[(mb+grp)*65+k8+qq+4], Ah3 = sAh[(mb+grp+8)*65+k8+qq+4];
            unsigned Al0 = sAl[(mb+grp)*65+k8+qq],   Al1 = sAl[(mb+grp+8)*65+k8+qq];
            unsigned Al2 = sAl[(mb+grp)*65+k8+qq+4], Al3 = sAl[(mb+grp+8)*65+k8+qq+4];
            unsigned Bh0 = sWh[(wn*8+grp)*65+k8+qq], Bh1 = sWh[(wn*8+grp)*65+k8+qq+4];
            unsigned Bl0 = sWl[(wn*8+grp)*65+k8+qq], Bl1 = sWl[(wn*8+grp)*65+k8+qq+4];
            mma16816(cacc, Ah0,Ah1,Ah2,Ah3, Bh0,Bh1);
            mma16816(cacc, Ah0,Ah1,Ah2,Ah3, Bl0,Bl1);
            mma16816(cacc, Al0,Al1,Al2,Al3, Bh0,Bh1);
        }
        buf ^= 1;
    }
}

#define CELL_SMEM (2*STG*4)

// ---------------------------------------------------------------------------
// cell body: gates-GEMM(s) + LSTM cell update. Shared by cell32 / cell_mega.
// ---------------------------------------------------------------------------
struct CArg {
    const float* A1; const unsigned* W1; int K1;
    const float* A2; const unsigned* W2; int K2;
    int NH;
    const float* gadd; int gaddB;
    float* cst;
    float* hout;
    float* out2; int out2B;
};

__device__ __forceinline__ void cell_run(const CArg& p, unsigned* smx, int tid, int& buf) {
    int r = tid >> 3, c8 = tid & 7;
    int lane = tid & 31, wid = tid >> 5;
    int mh = wid & 1, wn = wid >> 1, grp = lane >> 2, qq = lane & 3;
    int j0 = blockIdx.x * 8;
    size_t wrow = (size_t)(r >> 3)*p.NH + j0 + (r & 7);

    float cacc[4] = {0.f, 0.f, 0.f, 0.f};
    kloop2(p.A1 + (size_t)r*p.K1, p.W1 + wrow*p.K1, p.K1,
           smx, cacc, r, c8, mh, wn, grp, qq, buf);
    if (p.K2)
        kloop2(p.A2 + (size_t)r*p.K2, p.W2 + wrow*p.K2, p.K2,
               smx, cacc, r, c8, mh, wn, grp, qq, buf);

    __syncthreads();
    float (*gsm)[33] = (float(*)[33])smx;
    int n = wn*8 + 2*qq;
    int b0 = mh*16 + grp;
    gsm[b0][n]   = cacc[0]; gsm[b0][n+1]   = cacc[1];
    gsm[b0+8][n] = cacc[2]; gsm[b0+8][n+1] = cacc[3];
    __syncthreads();

    int b = tid & 31, jj = tid >> 5, j = j0 + jj;
    size_t gb = (size_t)b * p.gaddB;
    float gi = gsm[b][jj]      + p.gadd[gb + 0*p.NH + j];
    float gf = gsm[b][8+jj]    + p.gadd[gb + 1*p.NH + j];
    float gg = gsm[b][16+jj]   + p.gadd[gb + 2*p.NH + j];
    float go = gsm[b][24+jj]   + p.gadd[gb + 3*p.NH + j];
    int ci = b*p.NH + j;
    float cc = sigf(gf)*p.cst[ci] + sigf(gi)*tanhf(gg);
    p.cst[ci] = cc;
    float hh = sigf(go)*tanhf(cc);
    p.hout[ci] = hh;
    if (p.out2) p.out2[(size_t)b*p.out2B + j] = hh;
}

// encoder: one step, both directions (blockIdx.y selects)
__global__ __launch_bounds__(256) void cell32(CArg pa, CArg pb) {
    const CArg p = blockIdx.y ? pb : pa;
    extern __shared__ unsigned smx[];
    int buf = 0;
    cell_run(p, smx, threadIdx.x, buf);
}

// decoder: cell0 -> grid barrier -> cell1, one launch
__global__ __launch_bounds__(256) void cell_mega(CArg pa, CArg pb, unsigned tgt) {
    extern __shared__ unsigned smx[];
    int buf = 0;
    cell_run(pa, smx, threadIdx.x, buf);
    gwait(&g_barC, tgt);
    cell_run(pb, smx, threadIdx.x, buf);
}

// ---------------------------------------------------------------------------
// attn_mega: q-GEMV -> gbar -> scores -> gbar -> softmax+context. 256 blocks.
// ---------------------------------------------------------------------------
__global__ __launch_bounds__(256) void attn_mega(
    const float* __restrict__ h1r, const unsigned* __restrict__ Wa,
    const float* __restrict__ Wa_b, const float* __restrict__ va,
    unsigned tbase)
{
    extern __shared__ unsigned smx[];
    __shared__ float wsm[SS];
    int bid = blockIdx.x, tid = threadIdx.x;

    // phase 0: q = h1 @ Wa^T + Wa_b  (blocks 0..31, 32 N-tiles)
    if (bid < 32) {
        int r = tid >> 3, c8 = tid & 7;
        int lane = tid & 31, wid = tid >> 5;
        int mh = wid & 1, wn = wid >> 1, grp = lane >> 2, qq = lane & 3;
        int n0 = bid * 32;
        float cacc[4] = {0.f, 0.f, 0.f, 0.f};
        int buf = 0;
        kloop2(h1r + (size_t)r*DDm, Wa + (size_t)(n0 + r)*DDm, DDm,
               smx, cacc, r, c8, mh, wn, grp, qq, buf);
        int gn = n0 + wn*8 + 2*qq;
        int b0 = mh*16 + grp;
        g_q[(size_t)b0*DDm + gn]       = cacc[0] + Wa_b[gn];
        g_q[(size_t)b0*DDm + gn + 1]   = cacc[1] + Wa_b[gn+1];
        g_q[(size_t)(b0+8)*DDm + gn]   = cacc[2] + Wa_b[gn];
        g_q[(size_t)(b0+8)*DDm + gn+1] = cacc[3] + Wa_b[gn+1];
    }
    gwait(&g_barA, tbase + 256);

    // phase 1: scores (warp per (b,s))
    {
        int lane = tid & 31, w = tid >> 5;
        int task = bid*8 + w;
        int b = task >> 6;
        const float* u  = g_Uenc + (size_t)task*DDm;
        const float* qq = g_q + (size_t)b*DDm;
        float p = 0.f;
        #pragma unroll 8
        for (int e = lane; e < DDm; e += 32)
            p += va[e]*tanha(qq[e] + u[e]);
        #pragma unroll
        for (int off = 16; off; off >>= 1)
            p += __shfl_xor_sync(0xffffffffu, p, off);
        if (lane == 0) g_sc[task] = p;
    }
    gwait(&g_barA, tbase + 512);

    // phase 2: softmax + context (blocks 0..127; (b, quarter))
    if (bid < 128) {
        int b = bid >> 2, quarter = bid & 3;
        if (tid < SS) wsm[tid] = g_sc[b*SS + tid];
        __syncthreads();
        if (tid == 0) {
            float mx = wsm[0];
            for (int s = 1; s < SS; s++) mx = fmaxf(mx, wsm[s]);
            float sm = 0.f;
            for (int s = 0; s < SS; s++) { wsm[s] = expf(wsm[s]-mx); sm += wsm[s]; }
            float inv = 1.0f/sm;
            for (int s = 0; s < SS; s++) wsm[s] *= inv;
        }
        __syncthreads();
        int d = quarter*256 + tid;
        float acc = 0.f;
        const float* e = g_enc + (size_t)(b*SS)*DDm + d;
        #pragma unroll 8
        for (int s = 0; s < SS; s++) acc += wsm[s]*e[(size_t)s*DDm];
        g_xcat[(size_t)b*DDm + d] = acc;
    }
}

// ---------------------------------------------------------------------------
// decoder initial state
// ---------------------------------------------------------------------------
__global__ void dec_init() {
    int idx = blockIdx.x*256 + threadIdx.x;
    if (idx >= BB*HH) return;
    int b = idx >> 9, j = idx & 511;
    const int NP = BB*HH;
    float h0f = g_hbuf[(size_t)((0*2+0)*2+0)*NP + idx];
    float h0b = g_hbuf[(size_t)((0*2+1)*2+0)*NP + idx];
    float h1f = g_hbuf[(size_t)((1*2+0)*2+0)*NP + idx];
    float h1b = g_hbuf[(size_t)((1*2+1)*2+0)*NP + idx];
    float c0f = g_c[(size_t)(0*2+0)*NP + idx];
    float c0b = g_c[(size_t)(0*2+1)*NP + idx];
    float c1f = g_c[(size_t)(1*2+0)*NP + idx];
    float c1b = g_c[(size_t)(1*2+1)*NP + idx];
    g_dh0[b*DDm + j]      = h0f;  g_dh0[b*DDm + HH + j] = h0b;
    g_dc0[b*DDm + j]      = c0f;  g_dc0[b*DDm + HH + j] = c0b;
    g_dh1[b*DDm + j]      = h1f;  g_dh1[b*DDm + HH + j] = h1b;
    g_dc1[b*DDm + j]      = c1f;  g_dc1[b*DDm + HH + j] = c1b;
}

// ---------------------------------------------------------------------------
// host driver
// ---------------------------------------------------------------------------
static float* symf(const void* s) {
    void* p = nullptr;
    cudaGetSymbolAddress(&p, s);
    return (float*)p;
}

extern "C" void kernel_launch(void* const* d_in, const int* in_sizes, int n_in,
                              void* d_out, int out_size) {
    const int*   x        = (const int*)  d_in[0];
    const int*   y        = (const int*)  d_in[1];
    const float* emb_src  = (const float*)d_in[2];
    const float* emb_tgt  = (const float*)d_in[3];
    const float* e0f_wih  = (const float*)d_in[4];
    const float* e0f_whh  = (const float*)d_in[5];
    const float* e0f_b    = (const float*)d_in[6];
    const float* e0b_wih  = (const float*)d_in[7];
    const float* e0b_whh  = (const float*)d_in[8];
    const float* e0b_b    = (const float*)d_in[9];
    const float* e1f_wih  = (const float*)d_in[10];
    const float* e1f_whh  = (const float*)d_in[11];
    const float* e1f_b    = (const float*)d_in[12];
    const float* e1b_wih  = (const float*)d_in[13];
    const float* e1b_whh  = (const float*)d_in[14];
    const float* e1b_b    = (const float*)d_in[15];
    const float* Wa_w     = (const float*)d_in[16];
    const float* Wa_b     = (const float*)d_in[17];
    const float* Ua_w     = (const float*)d_in[18];
    const float* Ua_b     = (const float*)d_in[19];
    const float* va_w     = (const float*)d_in[20];
    const float* d0_wih   = (const float*)d_in[21];
    const float* d0_whh   = (const float*)d_in[22];
    const float* d0_b     = (const float*)d_in[23];
    const float* d1_wih   = (const float*)d_in[24];
    const float* d1_whh   = (const float*)d_in[25];
    const float* d1_b     = (const float*)d_in[26];
    const float* fc_w     = (const float*)d_in[27];
    const float* fc_b     = (const float*)d_in[28];
    float* out = (float*)d_out;

    float* p_embx = symf(g_embx);
    float* p_xgF  = symf(g_xgF);
    float* p_xgB  = symf(g_xgB);
    float* p_in1  = symf(g_in1);
    float* p_enc  = symf(g_enc);
    float* p_hbuf = symf(g_hbuf);
    float* p_c    = symf(g_c);
    float* p_dh0  = symf(g_dh0);
    float* p_dc0  = symf(g_dc0);
    float* p_dh1  = symf(g_dh1);
    float* p_dc1  = symf(g_dc1);
    float* p_xcat = symf(g_xcat);
    float* p_H1   = symf(g_H1);
    float* p_Gemb = symf(g_Gemb);
    unsigned* p_w     = (unsigned*)symf(g_wcvt);
    unsigned* p_embxc = (unsigned*)symf(g_embxc);
    unsigned* p_in1c  = (unsigned*)symf(g_in1c);
    unsigned* p_encc  = (unsigned*)symf(g_encc);
    unsigned* p_H1c   = (unsigned*)symf(g_H1c);
    unsigned* p_embTc = (unsigned*)symf(g_embTc);
    void* p_barA = nullptr; cudaGetSymbolAddress(&p_barA, g_barA);
    void* p_barC = nullptr; cudaGetSymbolAddress(&p_barC, g_barC);

    cudaFuncSetAttribute(cell32,    cudaFuncAttributeMaxDynamicSharedMemorySize, CELL_SMEM);
    cudaFuncSetAttribute(cell_mega, cudaFuncAttributeMaxDynamicSharedMemorySize, CELL_SMEM);
    cudaFuncSetAttribute(attn_mega, cudaFuncAttributeMaxDynamicSharedMemorySize, CELL_SMEM);

    static cudaStream_t s2 = nullptr;
    static cudaEvent_t evStart, evA, evH[4], evEnd;
    if (!s2) {
        cudaStreamCreateWithFlags(&s2, cudaStreamNonBlocking);
        cudaEventCreateWithFlags(&evStart, cudaEventDisableTiming);
        cudaEventCreateWithFlags(&evA,     cudaEventDisableTiming);
        for (int i = 0; i < 4; i++) cudaEventCreateWithFlags(&evH[i], cudaEventDisableTiming);
        cudaEventCreateWithFlags(&evEnd,   cudaEventDisableTiming);
    }

    const int M = BB*SS;   // 2048

    // ---- fork: stream2 — decoder/attention weights, Gemb GEMM, fc weights ----
    cudaEventRecord(evStart, 0);
    cudaStreamWaitEvent(s2, evStart, 0);
    cudaMemsetAsync(p_H1c + 2016ull*DDm, 0, 32ull*DDm*sizeof(unsigned), s2);
    {
        struct { const float* s; size_t off; size_t n; } cv2[5] = {
            { Ua_w,   OFF_UA,    1024ull*1024 },
            { Wa_w,   OFF_WA,    1024ull*1024 },
            { d0_whh, OFF_D0WHH, 4096ull*1024 },
            { d1_wih, OFF_D1WIH, 4096ull*1024 },
            { d1_whh, OFF_D1WHH, 4096ull*1024 },
        };
        for (int i = 0; i < 5; i++)
            cvtW4<<<1024, 256, 0, s2>>>((const float4*)cv2[i].s,
                                        (uint4*)(p_w + cv2[i].off), (int)(cv2[i].n/4));
    }
    // d0_wih split into emb-cols and ctx-cols
    cvtW4s<<<1024, 256, 0, s2>>>(d0_wih, (uint4*)(p_w + OFF_D0WIHE), 4096, 1536, 0, 512);
    cvtW4s<<<1024, 256, 0, s2>>>(d0_wih, (uint4*)(p_w + OFF_D0WIHC), 4096, 1536, 512, 1024);
    // precompute embedding gate adds for all steps: Gemb = embT @ d0_wih_emb^T + d0_b
    gath_tgt<<<2048, 128, 0, s2>>>(y, emb_tgt);
    {
        dim3 grid(16, (4*DDm)/128);
        bgemm128<<<grid, 256, 0, s2>>>(p_embTc, p_w + OFF_D0WIHE, d0_b, p_Gemb,
                                       63*BB, 4*DDm, EE, 0, 0);
    }
    cudaEventRecord(evA, s2);
    cvtW4<<<1024, 256, 0, s2>>>((const float4*)fc_w, (uint4*)(p_w + OFF_FC),
                                (int)(32000ull*1024/4));

    // ---- main stream: encoder weights + encoder ----
    {
        struct { const float* s; size_t off; size_t n; } cv[8] = {
            { e0f_wih, OFF_E0F_WIH, 2048ull*512  },
            { e0b_wih, OFF_E0B_WIH, 2048ull*512  },
            { e1f_wih, OFF_E1F_WIH, 2048ull*1024 },
            { e1b_wih, OFF_E1B_WIH, 2048ull*1024 },
            { e0f_whh, OFF_E0F_WHH, 2048ull*512  },
            { e0b_whh, OFF_E0B_WHH, 2048ull*512  },
            { e1f_whh, OFF_E1F_WHH, 2048ull*512  },
            { e1b_whh, OFF_E1B_WHH, 2048ull*512  },
        };
        for (int i = 0; i < 8; i++)
            cvtW4<<<1024, 256>>>((const float4*)cv[i].s, (uint4*)(p_w + cv[i].off),
                                 (int)(cv[i].n/4));
    }

    embed_rev_kernel<<<BB*SS, 128>>>(x, emb_src);
    cvtW4<<<1024, 256>>>((const float4*)p_embx, (uint4*)p_embxc, BB*SS*EE/4);

    {
        dim3 grid(M/128, (4*HH)/128);
        bgemm128<<<grid, 256>>>(p_embxc, p_w + OFF_E0F_WIH, e0f_b, p_xgF, M, 4*HH, EE, 0, 0);
        bgemm128<<<grid, 256>>>(p_embxc, p_w + OFF_E0B_WIH, e0b_b, p_xgB, M, 4*HH, EE, 0, 0);
    }

    cudaMemsetAsync(p_hbuf, 0, sizeof(float)*2*2*2*BB*HH);
    cudaMemsetAsync(p_c,    0, sizeof(float)*2*2*BB*HH);
    cudaMemsetAsync(p_barA, 0, sizeof(unsigned));
    cudaMemsetAsync(p_barC, 0, sizeof(unsigned));

    const size_t whhOff[2][2] = { {OFF_E0F_WHH, OFF_E0B_WHH}, {OFF_E1F_WHH, OFF_E1B_WHH} };
    for (int layer = 0; layer < 2; layer++) {
        if (layer == 1) {
            cvtW4<<<1024, 256>>>((const float4*)p_in1, (uint4*)p_in1c, BB*SS*DDm/4);
            dim3 grid(M/128, (4*HH)/128);
            bgemm128<<<grid, 256>>>(p_in1c, p_w + OFF_E1F_WIH, e1f_b, p_xgF, M, 4*HH, DDm, 0, 0);
            bgemm128<<<grid, 256>>>(p_in1c, p_w + OFF_E1B_WIH, e1b_b, p_xgB, M, 4*HH, DDm, 0, 0);
        }
        float* outb = layer ? p_enc : p_in1;
        for (int s = 0; s < SS; s++) {
            int pp = s & 1;
            CArg a{}, bg{};
            a.A1 = p_hbuf + (size_t)((layer*2+0)*2 + pp)*(BB*HH);
            a.W1 = p_w + whhOff[layer][0]; a.K1 = HH;
            a.A2 = nullptr; a.W2 = nullptr; a.K2 = 0;
            a.NH = HH;
            a.gadd = p_xgF + (size_t)s*4*HH;  a.gaddB = SS*4*HH;
            a.cst  = p_c + (size_t)(layer*2+0)*(BB*HH);
            a.hout = p_hbuf + (size_t)((layer*2+0)*2 + (pp^1))*(BB*HH);
            a.out2 = outb + (size_t)s*DDm;    a.out2B = SS*DDm;
            int s1 = 63 - s;
            bg.A1 = p_hbuf + (size_t)((layer*2+1)*2 + pp)*(BB*HH);
            bg.W1 = p_w + whhOff[layer][1]; bg.K1 = HH;
            bg.A2 = nullptr; bg.W2 = nullptr; bg.K2 = 0;
            bg.NH = HH;
            bg.gadd = p_xgB + (size_t)s1*4*HH; bg.gaddB = SS*4*HH;
            bg.cst  = p_c + (size_t)(layer*2+1)*(BB*HH);
            bg.hout = p_hbuf + (size_t)((layer*2+1)*2 + (pp^1))*(BB*HH);
            bg.out2 = outb + (size_t)s1*DDm + HH; bg.out2B = SS*DDm;
            cell32<<<dim3(HH/8, 2), 256, CELL_SMEM>>>(a, bg);
        }
    }

    // join: decoder weights + Gemb ready
    cudaStreamWaitEvent(0, evA, 0);

    // Uenc = enc @ Ua^T + Ua_b
    cvtW4<<<1024, 256>>>((const float4*)p_enc, (uint4*)p_encc, BB*SS*DDm/4);
    {
        dim3 grid(M/128, DDm/128);
        bgemm128<<<grid, 256>>>(p_encc, p_w + OFF_UA, Ua_b, symf(g_Uenc), M, DDm, DDm, 0, 0);
    }

    dec_init<<<(BB*HH + 255)/256, 256>>>();

    // decoder: 2 kernels per step; fc chunks forked to s2
    int chunkIdx = 0;
    for (int t = 0; t < TT-1; t++) {
        int pp = t & 1;
        float* h0r = p_dh0 + (size_t)pp*(BB*DDm);
        float* h0w = p_dh0 + (size_t)(pp^1)*(BB*DDm);
        float* h1r = p_dh1 + (size_t)pp*(BB*DDm);
        float* h1w = p_dh1 + (size_t)(pp^1)*(BB*DDm);

        attn_mega<<<256, 256, CELL_SMEM>>>(h1r, p_w + OFF_WA, Wa_b, va_w,
                                           (unsigned)(t*512));

        CArg c0{}, c1{};
        c0.A1 = p_xcat; c0.W1 = p_w + OFF_D0WIHC; c0.K1 = DDm;
        c0.A2 = h0r;    c0.W2 = p_w + OFF_D0WHH;  c0.K2 = DDm;
        c0.NH = DDm;
        c0.gadd = p_Gemb + (size_t)t*BB*4*DDm; c0.gaddB = 4*DDm;
        c0.cst = p_dc0; c0.hout = h0w; c0.out2 = nullptr; c0.out2B = 0;

        c1.A1 = h0w; c1.W1 = p_w + OFF_D1WIH; c1.K1 = DDm;
        c1.A2 = h1r; c1.W2 = p_w + OFF_D1WHH; c1.K2 = DDm;
        c1.NH = DDm; c1.gadd = d1_b; c1.gaddB = 0;
        c1.cst = p_dc1; c1.hout = h1w;
        c1.out2 = p_H1 + (size_t)t*BB*DDm; c1.out2B = DDm;

        cell_mega<<<128, 256, CELL_SMEM>>>(c0, c1, (unsigned)((t+1)*128));

        if (t == 15 || t == 31 || t == 47 || t == 62) {
            int t0 = chunkIdx * 16;
            int rows = (chunkIdx < 3) ? 512 : 480;
            cudaEventRecord(evH[chunkIdx], 0);
            cudaStreamWaitEvent(s2, evH[chunkIdx], 0);
            cvtW4<<<1024, 256, 0, s2>>>(
                (const float4*)(p_H1 + (size_t)t0*BB*DDm),
                (uint4*)(p_H1c + (size_t)t0*BB*DDm),
                rows*DDm/4);
            dim3 grid(4, VV/128);
            bgemm128<<<grid, 256, 0, s2>>>(p_H1c, p_w + OFF_FC, fc_b, out,
                                           63*BB, VV, DDm, 1, t0*BB);
            chunkIdx++;
        }
    }

    cudaEventRecord(evEnd, s2);
    cudaStreamWaitEvent(0, evEnd, 0);
}

// round 17
// speedup vs baseline: 1.0894x; 1.0894x over previous
#include <cuda_runtime.h>
#include <cuda_bf16.h>
#include <math.h>

// Problem constants
#define BB   32      // batch
#define SS   64      // src len
#define TT   64      // tgt len (63 decode steps)
#define EE   512     // embed dim
#define HH   512     // encoder hidden per dir
#define DDm  1024    // 2*H
#define VV   32000   // vocab

// ---------------------------------------------------------------------------
// Static device scratch
// ---------------------------------------------------------------------------
__device__ __align__(16) float g_embx [BB*SS*EE];
__device__ __align__(16) float g_xgF  [BB*SS*4*HH];
__device__ __align__(16) float g_xgB  [BB*SS*4*HH];
__device__ __align__(16) float g_in1  [BB*SS*DDm];
__device__ __align__(16) float g_enc  [BB*SS*DDm];
__device__ __align__(16) float g_Uenc [BB*SS*DDm];
__device__ __align__(16) float g_hbuf [2*2*2*BB*HH];   // fp32 h (for dec_init)
__device__ __align__(16) float g_c    [2*2*BB*HH];
__device__ __align__(16) float g_dc0  [BB*DDm];
__device__ __align__(16) float g_dc1  [BB*DDm];
__device__ __align__(16) float g_q    [BB*DDm];
__device__ __align__(16) float g_sc   [BB*SS];
__device__ __align__(16) float g_Gemb [2048*4*DDm];    // emb gate adds (+d0_b), rows t*32+b

// u32 (split-bf16 packed) activation buffers
__device__ __align__(16) unsigned g_hbufc[2*2*2*BB*HH];  // encoder recurrent h
__device__ __align__(16) unsigned g_dh0c [2*BB*DDm];     // decoder h0 ping-pong
__device__ __align__(16) unsigned g_dh1c [2*BB*DDm];     // decoder h1 ping-pong
__device__ __align__(16) unsigned g_xcatc[BB*DDm];       // context
__device__ __align__(16) unsigned g_embxc[BB*SS*EE];
__device__ __align__(16) unsigned g_in1c [BB*SS*DDm];
__device__ __align__(16) unsigned g_encc [BB*SS*DDm];
__device__ __align__(16) unsigned g_H1c  [2048*DDm];     // decoder h1 history (padded)
__device__ __align__(16) unsigned g_embTc[2048*EE];      // target embeddings

// converted-weight pool
#define OFF_E0F_WIH 0ull
#define OFF_E0B_WIH (OFF_E0F_WIH + 2048ull*512)
#define OFF_E1F_WIH (OFF_E0B_WIH + 2048ull*512)
#define OFF_E1B_WIH (OFF_E1F_WIH + 2048ull*1024)
#define OFF_E0F_WHH (OFF_E1B_WIH + 2048ull*1024)
#define OFF_E0B_WHH (OFF_E0F_WHH + 2048ull*512)
#define OFF_E1F_WHH (OFF_E0B_WHH + 2048ull*512)
#define OFF_E1B_WHH (OFF_E1F_WHH + 2048ull*512)
#define OFF_UA      (OFF_E1B_WHH + 2048ull*512)
#define OFF_WA      (OFF_UA + 1024ull*1024)
#define OFF_D0WIHE  (OFF_WA + 1024ull*1024)            // d0_wih cols [0,512)
#define OFF_D0WIHC  (OFF_D0WIHE + 4096ull*512)         // d0_wih cols [512,1536)
#define OFF_D0WHH   (OFF_D0WIHC + 4096ull*1024)
#define OFF_D1WIH   (OFF_D0WHH + 4096ull*1024)
#define OFF_D1WHH   (OFF_D1WIH + 4096ull*1024)
#define OFF_FC      (OFF_D1WHH + 4096ull*1024)
#define WCVT_TOTAL  (OFF_FC + 32000ull*1024)
__device__ __align__(16) unsigned g_wcvt[WCVT_TOTAL];

__device__ __forceinline__ float sigf(float v) { return 1.0f/(1.0f + expf(-v)); }

__device__ __forceinline__ float tanha(float x) {
    float r; asm("tanh.approx.f32 %0, %1;" : "=f"(r) : "f"(x)); return r;
}

// fp32 pair -> packed (bf16 hi, bf16 lo)
__device__ __forceinline__ void cvt2(float f0, float f1, unsigned& hi, unsigned& lo) {
    __nv_bfloat16 h0 = __float2bfloat16(f0);
    __nv_bfloat16 h1 = __float2bfloat16(f1);
    __nv_bfloat16 l0 = __float2bfloat16(f0 - __bfloat162float(h0));
    __nv_bfloat16 l1 = __float2bfloat16(f1 - __bfloat162float(h1));
    hi = (unsigned)__bfloat16_as_ushort(h0) | ((unsigned)__bfloat16_as_ushort(h1) << 16);
    lo = (unsigned)__bfloat16_as_ushort(l0) | ((unsigned)__bfloat16_as_ushort(l1) << 16);
}

__device__ __forceinline__ void mma16816(float* c,
    unsigned a0, unsigned a1, unsigned a2, unsigned a3,
    unsigned b0, unsigned b1)
{
    asm volatile(
        "mma.sync.aligned.m16n8k16.row.col.f32.bf16.bf16.f32 "
        "{%0,%1,%2,%3}, {%4,%5,%6,%7}, {%8,%9}, {%0,%1,%2,%3};"
        : "+f"(c[0]), "+f"(c[1]), "+f"(c[2]), "+f"(c[3])
        : "r"(a0), "r"(a1), "r"(a2), "r"(a3), "r"(b0), "r"(b1));
}

// ---------------------------------------------------------------------------
// conversions
// ---------------------------------------------------------------------------
__global__ void cvtW4(const float4* __restrict__ src, uint4* __restrict__ dst, int n4) {
    for (int i = blockIdx.x*blockDim.x + threadIdx.x; i < n4; i += gridDim.x*blockDim.x) {
        float4 v = src[i];
        unsigned h0, l0, h1, l1;
        cvt2(v.x, v.y, h0, l0);
        cvt2(v.z, v.w, h1, l1);
        dst[i] = make_uint4(h0, l0, h1, l1);
    }
}

// strided column-slice conversion
__global__ void cvtW4s(const float* __restrict__ src, uint4* __restrict__ dst,
                       int rows, int rs, int c0, int Kc) {
    int n4 = rows * (Kc/4);
    for (int i = blockIdx.x*blockDim.x + threadIdx.x; i < n4; i += gridDim.x*blockDim.x) {
        int row = i / (Kc/4), cf = i % (Kc/4);
        float4 v = *(const float4*)(src + (size_t)row*rs + c0 + cf*4);
        unsigned h0, l0, h1, l1;
        cvt2(v.x, v.y, h0, l0);
        cvt2(v.z, v.w, h1, l1);
        dst[i] = make_uint4(h0, l0, h1, l1);
    }
}

// gather + convert target embeddings: row (t*32+b) -> emb_tgt[y[b][t]], pad zeros
__global__ void gath_tgt(const int* __restrict__ y, const float* __restrict__ emb_tgt) {
    int row = blockIdx.x;
    int t = row >> 5, b = row & 31;
    uint4* dst = (uint4*)(g_embTc + (size_t)row*EE);
    int i = threadIdx.x;
    if (t < TT-1) {
        float4 v = ((const float4*)(emb_tgt + (size_t)y[b*TT+t]*EE))[i];
        unsigned h0, l0, h1, l1;
        cvt2(v.x, v.y, h0, l0);
        cvt2(v.z, v.w, h1, l1);
        dst[i] = make_uint4(h0, l0, h1, l1);
    } else {
        dst[i] = make_uint4(0u, 0u, 0u, 0u);
    }
}

// ---------------------------------------------------------------------------
// embedding gather with source reversal
// ---------------------------------------------------------------------------
__global__ void embed_rev_kernel(const int* __restrict__ x,
                                 const float* __restrict__ emb_src) {
    int bs = blockIdx.x;
    int b = bs >> 6, s = bs & 63;
    int tok = x[b*SS + (SS-1 - s)];
    const float4* src = (const float4*)(emb_src + (size_t)tok*EE);
    float4* dst = (float4*)(g_embx + (size_t)bs*EE);
    for (int i = threadIdx.x; i < EE/4; i += blockDim.x) dst[i] = src[i];
}

// ---------------------------------------------------------------------------
// bgemm128: split-bf16 mma GEMM, BM=BN=128, BK=32, register prefetch.
// ---------------------------------------------------------------------------
__global__ __launch_bounds__(256) void bgemm128(
    const unsigned* __restrict__ Ahl, const unsigned* __restrict__ Whl,
    const float* __restrict__ bias, float* __restrict__ C,
    int Mtot, int N, int K, int remap, int mbase)
{
    __shared__ unsigned sAh[128][17], sAl[128][17];
    __shared__ unsigned sWh[128][17], sWl[128][17];

    int tid = threadIdx.x;
    int m0 = mbase + blockIdx.x * 128;
    int n0 = blockIdx.y * 128;

    int lane = tid & 31, wid = tid >> 5;
    int wm = (wid & 3) * 32;
    int wn = (wid >> 2) * 64;
    int grp = lane >> 2, q = lane & 3;

    float c[2][8][4];
    #pragma unroll
    for (int mf = 0; mf < 2; mf++)
        #pragma unroll
        for (int nf = 0; nf < 8; nf++)
            #pragma unroll
            for (int i = 0; i < 4; i++) c[mf][nf][i] = 0.f;

    int r  = tid >> 1;
    int ku = (tid & 1) * 16;
    int kp = (tid & 1) * 8;

    const unsigned* Arow = Ahl + (size_t)(m0 + r)*K + ku;
    const unsigned* Wrow = Whl + (size_t)(n0 + r)*K + ku;

    uint4 pa[4], pw[4];
    #pragma unroll
    for (int i = 0; i < 4; i++) {
        pa[i] = *(const uint4*)(Arow + i*4);
        pw[i] = *(const uint4*)(Wrow + i*4);
    }

    for (int k0 = 0; k0 < K; k0 += 32) {
        __syncthreads();
        #pragma unroll
        for (int i = 0; i < 4; i++) {
            sAh[r][kp+2*i]   = pa[i].x; sAl[r][kp+2*i]   = pa[i].y;
            sAh[r][kp+2*i+1] = pa[i].z; sAl[r][kp+2*i+1] = pa[i].w;
            sWh[r][kp+2*i]   = pw[i].x; sWl[r][kp+2*i]   = pw[i].y;
            sWh[r][kp+2*i+1] = pw[i].z; sWl[r][kp+2*i+1] = pw[i].w;
        }
        __syncthreads();
        if (k0 + 32 < K) {
            #pragma unroll
            for (int i = 0; i < 4; i++) {
                pa[i] = *(const uint4*)(Arow + k0 + 32 + i*4);
                pw[i] = *(const uint4*)(Wrow + k0 + 32 + i*4);
            }
        }

        #pragma unroll
        for (int ks = 0; ks < 2; ks++) {
            int k8 = ks*8;
            unsigned Ah0[2], Ah1[2], Ah2[2], Ah3[2];
            unsigned Al0[2], Al1[2], Al2[2], Al3[2];
            #pragma unroll
            for (int mf = 0; mf < 2; mf++) {
                int mb = wm + mf*16;
                Ah0[mf] = sAh[mb+grp  ][k8+q];   Ah1[mf] = sAh[mb+grp+8][k8+q];
                Ah2[mf] = sAh[mb+grp  ][k8+q+4]; Ah3[mf] = sAh[mb+grp+8][k8+q+4];
                Al0[mf] = sAl[mb+grp  ][k8+q];   Al1[mf] = sAl[mb+grp+8][k8+q];
                Al2[mf] = sAl[mb+grp  ][k8+q+4]; Al3[mf] = sAl[mb+grp+8][k8+q+4];
            }
            #pragma unroll
            for (int nf = 0; nf < 8; nf++) {
                int nb = wn + nf*8;
                unsigned Bh0 = sWh[nb+grp][k8+q], Bh1 = sWh[nb+grp][k8+q+4];
                unsigned Bl0 = sWl[nb+grp][k8+q], Bl1 = sWl[nb+grp][k8+q+4];
                #pragma unroll
                for (int mf = 0; mf < 2; mf++) {
                    mma16816(c[mf][nf], Ah0[mf],Ah1[mf],Ah2[mf],Ah3[mf], Bh0,Bh1);
                    mma16816(c[mf][nf], Ah0[mf],Ah1[mf],Ah2[mf],Ah3[mf], Bl0,Bl1);
                    mma16816(c[mf][nf], Al0[mf],Al1[mf],Al2[mf],Al3[mf], Bh0,Bh1);
                }
            }
        }
    }

    #pragma unroll
    for (int mf = 0; mf < 2; mf++) {
        #pragma unroll
        for (int nf = 0; nf < 8; nf++) {
            int gn = n0 + wn + nf*8 + q*2;
            float b0 = bias[gn], b1 = bias[gn+1];
            int gm0 = m0 + wm + mf*16 + grp;
            int gm1 = gm0 + 8;
            if (gm0 < Mtot) {
                int row = remap ? (gm0 & 31)*63 + (gm0 >> 5) : gm0;
                C[(size_t)row*N + gn]     = c[mf][nf][0] + b0;
                C[(size_t)row*N + gn + 1] = c[mf][nf][1] + b1;
            }
            if (gm1 < Mtot) {
                int row = remap ? (gm1 & 31)*63 + (gm1 >> 5) : gm1;
                C[(size_t)row*N + gn]     = c[mf][nf][2] + b0;
                C[(size_t)row*N + gn + 1] = c[mf][nf][3] + b1;
            }
        }
    }
}

// ---------------------------------------------------------------------------
// BM=32 K-loop, BK=128, double-buffered; BOTH operands pre-converted u32.
// ---------------------------------------------------------------------------
#define STG (4*2080)
__device__ __forceinline__ void kloop2u(
    const unsigned* __restrict__ Arow, const unsigned* __restrict__ Wrow, int K,
    unsigned* __restrict__ sm,
    float* cacc, int r, int c8, int mh, int wn, int grp, int qq, int& buf)
{
    uint4 ua[4], uw[4];
    #pragma unroll
    for (int i = 0; i < 4; i++) {
        ua[i] = *(const uint4*)(Arow + (c8 + i*8)*4);
        uw[i] = *(const uint4*)(Wrow + (c8 + i*8)*4);
    }
    for (int k0 = 0; k0 < K; k0 += 128) {
        unsigned* sAh = sm + buf*STG;
        unsigned* sAl = sAh + 2080;
        unsigned* sWh = sAh + 4160;
        unsigned* sWl = sAh + 6240;
        #pragma unroll
        for (int i = 0; i < 4; i++) {
            int col = (c8 + i*8)*2;
            sAh[r*65+col]   = ua[i].x; sAl[r*65+col]   = ua[i].y;
            sAh[r*65+col+1] = ua[i].z; sAl[r*65+col+1] = ua[i].w;
            sWh[r*65+col]   = uw[i].x; sWl[r*65+col]   = uw[i].y;
            sWh[r*65+col+1] = uw[i].z; sWl[r*65+col+1] = uw[i].w;
        }
        __syncthreads();
        if (k0 + 128 < K) {
            #pragma unroll
            for (int i = 0; i < 4; i++) {
                ua[i] = *(const uint4*)(Arow + k0 + 128 + (c8 + i*8)*4);
                uw[i] = *(const uint4*)(Wrow + k0 + 128 + (c8 + i*8)*4);
            }
        }
        #pragma unroll
        for (int ks = 0; ks < 8; ks++) {
            int k8 = ks*8;
            int mb = mh*16;
            unsigned Ah0 = sAh[(mb+grp)*65+k8+qq],   Ah1 = sAh[(mb+grp+8)*65+k8+qq];
            unsigned Ah2 = sAh[(mb+grp)*65+k8+qq+4], Ah3 = sAh[(mb+grp+8)*65+k8+qq+4];
            unsigned Al0 = sAl[(mb+grp)*65+k8+qq],   Al1 = sAl[(mb+grp+8)*65+k8+qq];
            unsigned Al2 = sAl[(mb+grp)*65+k8+qq+4], Al3 = sAl[(mb+grp+8)*65+k8+qq+4];
            unsigned Bh0 = sWh[(wn*8+grp)*65+k8+qq], Bh1 = sWh[(wn*8+grp)*65+k8+qq+4];
            unsigned Bl0 = sWl[(wn*8+grp)*65+k8+qq], Bl1 = sWl[(wn*8+grp)*65+k8+qq+4];
            mma16816(cacc, Ah0,Ah1,Ah2,Ah3, Bh0,Bh1);
            mma16816(cacc, Ah0,Ah1,Ah2,Ah3, Bl0,Bl1);
            mma16816(cacc, Al0,Al1,Al2,Al3, Bh0,Bh1);
        }
        buf ^= 1;
    }
}

#define CELL_SMEM (2*STG*4)

// ---------------------------------------------------------------------------
// cell: gates-GEMM(s) + LSTM cell update. All GEMM operands u32.
// Outputs: houtU (u32, always), houtF (fp32 opt), outF (fp32 opt), outU (opt)
// ---------------------------------------------------------------------------
struct CArg {
    const unsigned* A1; const unsigned* W1; int K1;
    const unsigned* A2; const unsigned* W2; int K2;
    int NH;
    const float* gadd; int gaddB;
    float* cst;
    unsigned* houtU;
    float* houtF;
    float* outF; int outFB;
    unsigned* outU; int outUB;
};

__device__ __forceinline__ void cell_run(const CArg& p, unsigned* smx, int tid) {
    int r = tid >> 3, c8 = tid & 7;
    int lane = tid & 31, wid = tid >> 5;
    int mh = wid & 1, wn = wid >> 1, grp = lane >> 2, qq = lane & 3;
    int j0 = blockIdx.x * 8;
    size_t wrow = (size_t)(r >> 3)*p.NH + j0 + (r & 7);

    float cacc[4] = {0.f, 0.f, 0.f, 0.f};
    int buf = 0;
    kloop2u(p.A1 + (size_t)r*p.K1, p.W1 + wrow*p.K1, p.K1,
            smx, cacc, r, c8, mh, wn, grp, qq, buf);
    if (p.K2)
        kloop2u(p.A2 + (size_t)r*p.K2, p.W2 + wrow*p.K2, p.K2,
                smx, cacc, r, c8, mh, wn, grp, qq, buf);

    __syncthreads();
    float (*gsm)[33] = (float(*)[33])smx;
    int n = wn*8 + 2*qq;
    int b0 = mh*16 + grp;
    gsm[b0][n]   = cacc[0]; gsm[b0][n+1]   = cacc[1];
    gsm[b0+8][n] = cacc[2]; gsm[b0+8][n+1] = cacc[3];
    __syncthreads();

    int b = tid & 31, jj = tid >> 5, j = j0 + jj;
    size_t gb = (size_t)b * p.gaddB;
    float gi = gsm[b][jj]      + p.gadd[gb + 0*p.NH + j];
    float gf = gsm[b][8+jj]    + p.gadd[gb + 1*p.NH + j];
    float gg = gsm[b][16+jj]   + p.gadd[gb + 2*p.NH + j];
    float go = gsm[b][24+jj]   + p.gadd[gb + 3*p.NH + j];
    int ci = b*p.NH + j;
    float cc = sigf(gf)*p.cst[ci] + sigf(gi)*tanhf(gg);
    p.cst[ci] = cc;
    float hh = sigf(go)*tanhf(cc);
    if (p.houtF) p.houtF[ci] = hh;
    if (p.outF)  p.outF[(size_t)b*p.outFB + j] = hh;

    __syncthreads();                  // all gate reads done before reuse
    gsm[b][jj] = hh;
    __syncthreads();
    if (tid < 128) {
        int b2 = tid & 31, pp2 = tid >> 5;         // 0..3 -> pairs (2pp2, 2pp2+1)
        float f0 = gsm[b2][2*pp2], f1 = gsm[b2][2*pp2+1];
        unsigned h, l;
        cvt2(f0, f1, h, l);
        int u = j0 + 2*pp2;
        p.houtU[(size_t)b2*p.NH + u]     = h;
        p.houtU[(size_t)b2*p.NH + u + 1] = l;
        if (p.outU) {
            p.outU[(size_t)b2*p.outUB + u]     = h;
            p.outU[(size_t)b2*p.outUB + u + 1] = l;
        }
    }
}

// encoder: one step, both directions (blockIdx.y selects)
__global__ __launch_bounds__(256) void cell32(CArg pa, CArg pb) {
    const CArg p = blockIdx.y ? pb : pa;
    extern __shared__ unsigned smx[];
    cell_run(p, smx, threadIdx.x);
}

// ---------------------------------------------------------------------------
// qgemm32: q = h1 @ Wa^T + bias (A is u32 h1c)
// ---------------------------------------------------------------------------
__global__ __launch_bounds__(256) void qgemm32(
    const unsigned* __restrict__ A, const unsigned* __restrict__ W,
    const float* __restrict__ bias, float* __restrict__ C, int K, int N)
{
    extern __shared__ unsigned smx[];
    int tid = threadIdx.x;
    int r = tid >> 3, c8 = tid & 7;
    int lane = tid & 31, wid = tid >> 5;
    int mh = wid & 1, wn = wid >> 1, grp = lane >> 2, qq = lane & 3;
    int n0 = blockIdx.x * 32;

    float cacc[4] = {0.f, 0.f, 0.f, 0.f};
    int buf = 0;
    kloop2u(A + (size_t)r*K, W + (size_t)(n0 + r)*K, K,
            smx, cacc, r, c8, mh, wn, grp, qq, buf);

    int gn = n0 + wn*8 + 2*qq;
    int b0 = mh*16 + grp;
    C[(size_t)b0*N + gn]       = cacc[0] + bias[gn];
    C[(size_t)b0*N + gn + 1]   = cacc[1] + bias[gn+1];
    C[(size_t)(b0+8)*N + gn]   = cacc[2] + bias[gn];
    C[(size_t)(b0+8)*N + gn+1] = cacc[3] + bias[gn+1];
}

// ---------------------------------------------------------------------------
// decoder initial state: concat finals, pack to u32, copy c
// ---------------------------------------------------------------------------
__global__ void dec_init2() {
    int P = blockIdx.x*256 + threadIdx.x;      // pair index
    if (P >= BB*(DDm/2)) return;
    int b = P / (DDm/2);
    int pr = P % (DDm/2);
    int j0f = 2*pr;
    const int NP = BB*HH;

    int dir = (j0f >= HH) ? 1 : 0;
    int jj  = j0f - dir*HH;
    float h0a = g_hbuf[(size_t)((0*2+dir)*2+0)*NP + b*HH + jj];
    float h0b = g_hbuf[(size_t)((0*2+dir)*2+0)*NP + b*HH + jj + 1];
    float h1a = g_hbuf[(size_t)((1*2+dir)*2+0)*NP + b*HH + jj];
    float h1b = g_hbuf[(size_t)((1*2+dir)*2+0)*NP + b*HH + jj + 1];
    float c0a = g_c[(size_t)(0*2+dir)*NP + b*HH + jj];
    float c0b = g_c[(size_t)(0*2+dir)*NP + b*HH + jj + 1];
    float c1a = g_c[(size_t)(1*2+dir)*NP + b*HH + jj];
    float c1b = g_c[(size_t)(1*2+dir)*NP + b*HH + jj + 1];

    unsigned h, l;
    cvt2(h0a, h0b, h, l);
    g_dh0c[(size_t)b*DDm + j0f] = h; g_dh0c[(size_t)b*DDm + j0f + 1] = l;
    cvt2(h1a, h1b, h, l);
    g_dh1c[(size_t)b*DDm + j0f] = h; g_dh1c[(size_t)b*DDm + j0f + 1] = l;
    g_dc0[b*DDm + j0f] = c0a; g_dc0[b*DDm + j0f + 1] = c0b;
    g_dc1[b*DDm + j0f] = c1a; g_dc1[b*DDm + j0f + 1] = c1b;
}

// ---------------------------------------------------------------------------
// attention scores: warp per (b,s)
// ---------------------------------------------------------------------------
__global__ __launch_bounds__(256) void att_scores2(const float* __restrict__ va) {
    int lane = threadIdx.x & 31, w = threadIdx.x >> 5;
    int task = blockIdx.x*8 + w;
    int b = task >> 6;
    const float* u  = g_Uenc + (size_t)task*DDm;
    const float* qq = g_q + (size_t)b*DDm;
    float p = 0.f;
    #pragma unroll 8
    for (int e = lane; e < DDm; e += 32)
        p += va[e]*tanha(qq[e] + u[e]);
    #pragma unroll
    for (int off = 16; off; off >>= 1)
        p += __shfl_xor_sync(0xffffffffu, p, off);
    if (lane == 0) g_sc[task] = p;
}

// ---------------------------------------------------------------------------
// softmax + context (packed to u32). grid 128 = (b, quarter).
// ---------------------------------------------------------------------------
__global__ __launch_bounds__(256) void softmax_ctx3() {
    __shared__ float w[SS];
    int b = blockIdx.x >> 2, quarter = blockIdx.x & 3;
    int tid = threadIdx.x;
    if (tid < SS) w[tid] = g_sc[b*SS + tid];
    __syncthreads();
    if (tid == 0) {
        float mx = w[0];
        for (int s = 1; s < SS; s++) mx = fmaxf(mx, w[s]);
        float sm = 0.f;
        for (int s = 0; s < SS; s++) { w[s] = expf(w[s]-mx); sm += w[s]; }
        float inv = 1.0f/sm;
        for (int s = 0; s < SS; s++) w[s] *= inv;
    }
    __syncthreads();
    int d = quarter*256 + tid;
    float acc = 0.f;
    const float* e = g_enc + (size_t)(b*SS)*DDm + d;
    #pragma unroll 8
    for (int s = 0; s < SS; s++) acc += w[s]*e[(size_t)s*DDm];
    float accN = __shfl_down_sync(0xffffffffu, acc, 1);
    if (!(tid & 1)) {
        unsigned h, l;
        cvt2(acc, accN, h, l);
        g_xcatc[(size_t)b*DDm + d]     = h;
        g_xcatc[(size_t)b*DDm + d + 1] = l;
    }
}

// ---------------------------------------------------------------------------
// host driver
// ---------------------------------------------------------------------------
static float* symf(const void* s) {
    void* p = nullptr;
    cudaGetSymbolAddress(&p, s);
    return (float*)p;
}

extern "C" void kernel_launch(void* const* d_in, const int* in_sizes, int n_in,
                              void* d_out, int out_size) {
    const int*   x        = (const int*)  d_in[0];
    const int*   y        = (const int*)  d_in[1];
    const float* emb_src  = (const float*)d_in[2];
    const float* emb_tgt  = (const float*)d_in[3];
    const float* e0f_wih  = (const float*)d_in[4];
    const float* e0f_whh  = (const float*)d_in[5];
    const float* e0f_b    = (const float*)d_in[6];
    const float* e0b_wih  = (const float*)d_in[7];
    const float* e0b_whh  = (const float*)d_in[8];
    const float* e0b_b    = (const float*)d_in[9];
    const float* e1f_wih  = (const float*)d_in[10];
    const float* e1f_whh  = (const float*)d_in[11];
    const float* e1f_b    = (const float*)d_in[12];
    const float* e1b_wih  = (const float*)d_in[13];
    const float* e1b_whh  = (const float*)d_in[14];
    const float* e1b_b    = (const float*)d_in[15];
    const float* Wa_w     = (const float*)d_in[16];
    const float* Wa_b     = (const float*)d_in[17];
    const float* Ua_w     = (const float*)d_in[18];
    const float* Ua_b     = (const float*)d_in[19];
    const float* va_w     = (const float*)d_in[20];
    const float* d0_wih   = (const float*)d_in[21];
    const float* d0_whh   = (const float*)d_in[22];
    const float* d0_b     = (const float*)d_in[23];
    const float* d1_wih   = (const float*)d_in[24];
    const float* d1_whh   = (const float*)d_in[25];
    const float* d1_b     = (const float*)d_in[26];
    const float* fc_w     = (const float*)d_in[27];
    const float* fc_b     = (const float*)d_in[28];
    float* out = (float*)d_out;

    float* p_embx = symf(g_embx);
    float* p_xgF  = symf(g_xgF);
    float* p_xgB  = symf(g_xgB);
    float* p_in1  = symf(g_in1);
    float* p_enc  = symf(g_enc);
    float* p_hbuf = symf(g_hbuf);
    float* p_c    = symf(g_c);
    float* p_dc0  = symf(g_dc0);
    float* p_dc1  = symf(g_dc1);
    float* p_Gemb = symf(g_Gemb);
    unsigned* p_w     = (unsigned*)symf(g_wcvt);
    unsigned* p_embxc = (unsigned*)symf(g_embxc);
    unsigned* p_in1c  = (unsigned*)symf(g_in1c);
    unsigned* p_encc  = (unsigned*)symf(g_encc);
    unsigned* p_H1c   = (unsigned*)symf(g_H1c);
    unsigned* p_embTc = (unsigned*)symf(g_embTc);
    unsigned* p_hbufc = (unsigned*)symf(g_hbufc);
    unsigned* p_dh0c  = (unsigned*)symf(g_dh0c);
    unsigned* p_dh1c  = (unsigned*)symf(g_dh1c);
    unsigned* p_xcatc = (unsigned*)symf(g_xcatc);

    cudaFuncSetAttribute(cell32,  cudaFuncAttributeMaxDynamicSharedMemorySize, CELL_SMEM);
    cudaFuncSetAttribute(qgemm32, cudaFuncAttributeMaxDynamicSharedMemorySize, CELL_SMEM);

    static cudaStream_t s2 = nullptr;
    static cudaEvent_t evStart, evA, evH[4], evEnd;
    if (!s2) {
        cudaStreamCreateWithFlags(&s2, cudaStreamNonBlocking);
        cudaEventCreateWithFlags(&evStart, cudaEventDisableTiming);
        cudaEventCreateWithFlags(&evA,     cudaEventDisableTiming);
        for (int i = 0; i < 4; i++) cudaEventCreateWithFlags(&evH[i], cudaEventDisableTiming);
        cudaEventCreateWithFlags(&evEnd,   cudaEventDisableTiming);
    }

    const int M = BB*SS;   // 2048

    // ---- fork: stream2 — decoder/attention weights, Gemb, fc weights ----
    cudaEventRecord(evStart, 0);
    cudaStreamWaitEvent(s2, evStart, 0);
    cudaMemsetAsync(p_H1c + 2016ull*DDm, 0, 32ull*DDm*sizeof(unsigned), s2);
    {
        struct { const float* s; size_t off; size_t n; } cv2[5] = {
            { Ua_w,   OFF_UA,    1024ull*1024 },
            { Wa_w,   OFF_WA,    1024ull*1024 },
            { d0_whh, OFF_D0WHH, 4096ull*1024 },
            { d1_wih, OFF_D1WIH, 4096ull*1024 },
            { d1_whh, OFF_D1WHH, 4096ull*1024 },
        };
        for (int i = 0; i < 5; i++)
            cvtW4<<<1024, 256, 0, s2>>>((const float4*)cv2[i].s,
                                        (uint4*)(p_w + cv2[i].off), (int)(cv2[i].n/4));
    }
    cvtW4s<<<1024, 256, 0, s2>>>(d0_wih, (uint4*)(p_w + OFF_D0WIHE), 4096, 1536, 0, 512);
    cvtW4s<<<1024, 256, 0, s2>>>(d0_wih, (uint4*)(p_w + OFF_D0WIHC), 4096, 1536, 512, 1024);
    gath_tgt<<<2048, 128, 0, s2>>>(y, emb_tgt);
    {
        dim3 grid(16, (4*DDm)/128);
        bgemm128<<<grid, 256, 0, s2>>>(p_embTc, p_w + OFF_D0WIHE, d0_b, p_Gemb,
                                       63*BB, 4*DDm, EE, 0, 0);
    }
    cudaEventRecord(evA, s2);
    cvtW4<<<1024, 256, 0, s2>>>((const float4*)fc_w, (uint4*)(p_w + OFF_FC),
                                (int)(32000ull*1024/4));

    // ---- main stream: encoder weights + encoder ----
    {
        struct { const float* s; size_t off; size_t n; } cv[8] = {
            { e0f_wih, OFF_E0F_WIH, 2048ull*512  },
            { e0b_wih, OFF_E0B_WIH, 2048ull*512  },
            { e1f_wih, OFF_E1F_WIH, 2048ull*1024 },
            { e1b_wih, OFF_E1B_WIH, 2048ull*1024 },
            { e0f_whh, OFF_E0F_WHH, 2048ull*512  },
            { e0b_whh, OFF_E0B_WHH, 2048ull*512  },
            { e1f_whh, OFF_E1F_WHH, 2048ull*512  },
            { e1b_whh, OFF_E1B_WHH, 2048ull*512  },
        };
        for (int i = 0; i < 8; i++)
            cvtW4<<<1024, 256>>>((const float4*)cv[i].s, (uint4*)(p_w + cv[i].off),
                                 (int)(cv[i].n/4));
    }

    embed_rev_kernel<<<BB*SS, 128>>>(x, emb_src);
    cvtW4<<<1024, 256>>>((const float4*)p_embx, (uint4*)p_embxc, BB*SS*EE/4);

    {
        dim3 grid(M/128, (4*HH)/128);
        bgemm128<<<grid, 256>>>(p_embxc, p_w + OFF_E0F_WIH, e0f_b, p_xgF, M, 4*HH, EE, 0, 0);
        bgemm128<<<grid, 256>>>(p_embxc, p_w + OFF_E0B_WIH, e0b_b, p_xgB, M, 4*HH, EE, 0, 0);
    }

    cudaMemsetAsync(p_hbufc, 0, sizeof(unsigned)*2*2*2*BB*HH);
    cudaMemsetAsync(p_hbuf,  0, sizeof(float)*2*2*2*BB*HH);
    cudaMemsetAsync(p_c,     0, sizeof(float)*2*2*BB*HH);

    const size_t whhOff[2][2] = { {OFF_E0F_WHH, OFF_E0B_WHH}, {OFF_E1F_WHH, OFF_E1B_WHH} };
    for (int layer = 0; layer < 2; layer++) {
        if (layer == 1) {
            cvtW4<<<1024, 256>>>((const float4*)p_in1, (uint4*)p_in1c, BB*SS*DDm/4);
            dim3 grid(M/128, (4*HH)/128);
            bgemm128<<<grid, 256>>>(p_in1c, p_w + OFF_E1F_WIH, e1f_b, p_xgF, M, 4*HH, DDm, 0, 0);
            bgemm128<<<grid, 256>>>(p_in1c, p_w + OFF_E1B_WIH, e1b_b, p_xgB, M, 4*HH, DDm, 0, 0);
        }
        float* outb = layer ? p_enc : p_in1;
        for (int s = 0; s < SS; s++) {
            int pp = s & 1;
            CArg a{}, bg{};
            a.A1 = p_hbufc + (size_t)((layer*2+0)*2 + pp)*(BB*HH);
            a.W1 = p_w + whhOff[layer][0]; a.K1 = HH;
            a.A2 = nullptr; a.W2 = nullptr; a.K2 = 0;
            a.NH = HH;
            a.gadd = p_xgF + (size_t)s*4*HH;  a.gaddB = SS*4*HH;
            a.cst  = p_c + (size_t)(layer*2+0)*(BB*HH);
            a.houtU = p_hbufc + (size_t)((layer*2+0)*2 + (pp^1))*(BB*HH);
            a.houtF = p_hbuf  + (size_t)((layer*2+0)*2 + (pp^1))*(BB*HH);
            a.outF = outb + (size_t)s*DDm;    a.outFB = SS*DDm;
            a.outU = nullptr; a.outUB = 0;
            int s1 = 63 - s;
            bg.A1 = p_hbufc + (size_t)((layer*2+1)*2 + pp)*(BB*HH);
            bg.W1 = p_w + whhOff[layer][1]; bg.K1 = HH;
            bg.A2 = nullptr; bg.W2 = nullptr; bg.K2 = 0;
            bg.NH = HH;
            bg.gadd = p_xgB + (size_t)s1*4*HH; bg.gaddB = SS*4*HH;
            bg.cst  = p_c + (size_t)(layer*2+1)*(BB*HH);
            bg.houtU = p_hbufc + (size_t)((layer*2+1)*2 + (pp^1))*(BB*HH);
            bg.houtF = p_hbuf  + (size_t)((layer*2+1)*2 + (pp^1))*(BB*HH);
            bg.outF = outb + (size_t)s1*DDm + HH; bg.outFB = SS*DDm;
            bg.outU = nullptr; bg.outUB = 0;
            cell32<<<dim3(HH/8, 2), 256, CELL_SMEM>>>(a, bg);
        }
    }

    // join: decoder weights + Gemb ready
    cudaStreamWaitEvent(0, evA, 0);

    // Uenc = enc @ Ua^T + Ua_b
    cvtW4<<<1024, 256>>>((const float4*)p_enc, (uint4*)p_encc, BB*SS*DDm/4);
    {
        dim3 grid(M/128, DDm/128);
        bgemm128<<<grid, 256>>>(p_encc, p_w + OFF_UA, Ua_b, symf(g_Uenc), M, DDm, DDm, 0, 0);
    }

    dec_init2<<<(BB*(DDm/2) + 255)/256, 256>>>();

    // decoder: 5 launches per step; fc chunks forked to s2
    int chunkIdx = 0;
    for (int t = 0; t < TT-1; t++) {
        int pp = t & 1;
        unsigned* h0r = p_dh0c + (size_t)pp*(BB*DDm);
        unsigned* h0w = p_dh0c + (size_t)(pp^1)*(BB*DDm);
        unsigned* h1r = p_dh1c + (size_t)pp*(BB*DDm);
        unsigned* h1w = p_dh1c + (size_t)(pp^1)*(BB*DDm);

        qgemm32<<<DDm/32, 256, CELL_SMEM>>>(h1r, p_w + OFF_WA, Wa_b, symf(g_q), DDm, DDm);
        att_scores2<<<256, 256>>>(va_w);
        softmax_ctx3<<<128, 256>>>();

        CArg c0{};
        c0.A1 = p_xcatc; c0.W1 = p_w + OFF_D0WIHC; c0.K1 = DDm;
        c0.A2 = h0r;     c0.W2 = p_w + OFF_D0WHH;  c0.K2 = DDm;
        c0.NH = DDm;
        c0.gadd = p_Gemb + (size_t)t*BB*4*DDm; c0.gaddB = 4*DDm;
        c0.cst = p_dc0; c0.houtU = h0w; c0.houtF = nullptr;
        c0.outF = nullptr; c0.outFB = 0; c0.outU = nullptr; c0.outUB = 0;
        cell32<<<dim3(DDm/8, 1), 256, CELL_SMEM>>>(c0, c0);

        CArg c1{};
        c1.A1 = h0w; c1.W1 = p_w + OFF_D1WIH; c1.K1 = DDm;
        c1.A2 = h1r; c1.W2 = p_w + OFF_D1WHH; c1.K2 = DDm;
        c1.NH = DDm; c1.gadd = d1_b; c1.gaddB = 0;
        c1.cst = p_dc1; c1.houtU = h1w; c1.houtF = nullptr;
        c1.outF = nullptr; c1.outFB = 0;
        c1.outU = p_H1c + (size_t)t*BB*DDm; c1.outUB = DDm;
        cell32<<<dim3(DDm/8, 1), 256, CELL_SMEM>>>(c1, c1);

        if (t == 15 || t == 31 || t == 47 || t == 62) {
            int t0 = chunkIdx * 16;
            cudaEventRecord(evH[chunkIdx], 0);
            cudaStreamWaitEvent(s2, evH[chunkIdx], 0);
            dim3 grid(4, VV/128);
            bgemm128<<<grid, 256, 0, s2>>>(p_H1c, p_w + OFF_FC, fc_b, out,
                                           63*BB, VV, DDm, 1, t0*BB);
            chunkIdx++;
        }
    }

    cudaEventRecord(evEnd, s2);
    cudaStreamWaitEvent(0, evEnd, 0);
}